// round 10
// baseline (speedup 1.0000x reference)
#include <cuda_runtime.h>
#include <cuda_fp16.h>
#include <cstdint>

// Problem constants
#define Bn 131072
#define Cn 128
#define En 128
#define TM 128              // samples per tile
#define NTILES (Bn / TM)    // 1024
#define NPERS 444           // persistent CTAs (3 per SM on 148 SMs)

// ArcFace constants (m = 1.0, s = 100)
#define COSM 0.5403023058681398f
#define SINM 0.8414709848078965f
#define THv  (-0.5403023058681398f)
#define MMv  0.8414709848078965f
#define Sv   100.0f
#define SHIFT 30.0f                 // exp(z-30): no overflow (z<=100.1), no harmful underflow
#define LOG2E 1.4426950408889634f
#define SH2   (SHIFT * LOG2E)       // shift in log2 domain

// Scratch (no allocation allowed -> device globals)
__device__ uint32_t g_wfrag[8192];   // 32KB: normalized weight fp16, HMMA fragment order
__device__ float    g_bsum[NPERS];
__device__ int      g_cnt;           // zero-init; reset by last CTA each launch

// smem layout
//   A: half[128][136] rows stride 272B        -> 34816 B
//   B: [tile][q][lane] uint4, zero padding    -> 32768 B
#define OFF_A    0
#define OFF_B    34816
#define OFF_RED  67584               // float[8]
#define OFF_FLAG 67616               // int
#define SMEM_SZ  67648

__device__ __forceinline__ float ex2(float x) {
    float r; asm("ex2.approx.f32 %0, %1;" : "=f"(r) : "f"(x)); return r;
}

__device__ __forceinline__ void hmma16816(float& c0, float& c1, float& c2, float& c3,
                                          uint32_t a0, uint32_t a1, uint32_t a2, uint32_t a3,
                                          uint32_t b0, uint32_t b1) {
    asm volatile(
        "mma.sync.aligned.m16n8k16.row.col.f32.f16.f16.f32 "
        "{%0,%1,%2,%3}, {%4,%5,%6,%7}, {%8,%9}, {%0,%1,%2,%3};"
        : "+f"(c0), "+f"(c1), "+f"(c2), "+f"(c3)
        : "r"(a0), "r"(a1), "r"(a2), "r"(a3), "r"(b0), "r"(b1));
}

// ---------------------------------------------------------------------------
// prep: normalize weight rows -> fragment-ordered fp16 global.
//   word for (tile t, lane, word w=2ks+b) at idx = (t*32 + lane)*16 + w
// ---------------------------------------------------------------------------
__global__ void prep_kernel(const float* __restrict__ weight)
{
    const int lane = threadIdx.x & 31;
    const int w    = threadIdx.x >> 5;
    const int row  = blockIdx.x * 8 + w;          // class n
    const int g    = row & 7;
    const int t    = row >> 3;

    float4 v = reinterpret_cast<const float4*>(weight)[row * 32 + lane];
    float ss = v.x * v.x + v.y * v.y + v.z * v.z + v.w * v.w;
    #pragma unroll
    for (int o = 16; o; o >>= 1) ss += __shfl_xor_sync(0xffffffffu, ss, o);
    float r = 1.0f / fmaxf(sqrtf(ss), 1e-12f);

    __half2 h0 = __floats2half2_rn(v.x * r, v.y * r);   // halves m = 2*lane
    __half2 h1 = __floats2half2_rn(v.z * r, v.w * r);   // halves m = 2*lane+1

    #pragma unroll
    for (int j = 0; j < 2; j++) {
        const int m  = 2 * lane + j;                     // m = k/2 = 8ks+4b+c
        const int c  = m & 3, b = (m >> 2) & 1, ks = m >> 3;
        const int di = (t * 32 + g * 4 + c) * 16 + 2 * ks + b;
        g_wfrag[di] = (j == 0) ? *(uint32_t*)&h0 : *(uint32_t*)&h1;
    }
}

// NLL from label-EXCLUDED shifted sum se = sum exp(z-30), and label cosine cs.
__device__ __forceinline__ float row_nll(float se, float cs) {
    float sn  = sqrtf(fmaxf(1.0f - cs * cs, 0.0f));
    float phi = (cs > THv) ? (cs * COSM - sn * SINM) : (cs - MMv);
    float zl  = Sv * phi;
    float se2 = se + ex2(fmaf(zl, LOG2E, -SH2));
    return (SHIFT + __logf(se2)) - zl;
}

// prefetch 8 rows of predict into registers
__device__ __forceinline__ void issue_p(const float* __restrict__ predict,
                                        int tile, int rowLocal, int lane, float4* Vp)
{
    const size_t base = ((size_t)tile * TM + rowLocal) * 32 + lane;
    const float4* p4 = (const float4*)predict;
    #pragma unroll
    for (int j = 0; j < 8; j++) Vp[j] = __ldg(p4 + base + (size_t)j * 32);
}

// consume 8 prefetched predict rows + direct-load target rows:
// fp16 convert + STS, butterfly -> row norm^2 + label
__device__ __forceinline__ void consume_half(const float4* Vp,
                                             const float* __restrict__ target,
                                             int tile, int rowLocal,
                                             char* sAbuf, int lane, int g,
                                             float& ssOut, int& lblOut)
{
    const size_t base = ((size_t)tile * TM + rowLocal) * 32 + lane;
    const float4* t4 = (const float4*)target;
    float ssq[8], lix[8];
    const float i0 = (float)(lane * 4), i1 = i0 + 1.f, i2 = i0 + 2.f, i3 = i0 + 3.f;
    #pragma unroll
    for (int j = 0; j < 8; j++) {
        float4 v = Vp[j];
        float4 t = __ldg(t4 + base + (size_t)j * 32);
        __half2 h0 = __floats2half2_rn(v.x, v.y);
        __half2 h1 = __floats2half2_rn(v.z, v.w);
        unsigned long long pk;
        asm("mov.b64 %0,{%1,%2};" : "=l"(pk)
            : "r"(*(uint32_t*)&h0), "r"(*(uint32_t*)&h1));
        *reinterpret_cast<unsigned long long*>(sAbuf + (rowLocal + j) * 272 + lane * 8) = pk;
        ssq[j] = fmaf(v.x, v.x, fmaf(v.y, v.y, fmaf(v.z, v.z, v.w * v.w)));
        lix[j] = fmaf(t.x, i0, fmaf(t.y, i1, fmaf(t.z, i2, t.w * i3)));
    }
    #pragma unroll
    for (int o = 16; o; o >>= 1) {
        #pragma unroll
        for (int i = 0; i < 8; i++) {
            ssq[i] += __shfl_xor_sync(0xffffffffu, ssq[i], o);
            lix[i] += __shfl_xor_sync(0xffffffffu, lix[i], o);
        }
    }
    float ss = 0.f, lf = 0.f;
    #pragma unroll
    for (int i = 0; i < 8; i++) if (i == g) { ss = ssq[i]; lf = lix[i]; }
    ssOut = ss; lblOut = (int)lf;
}

__device__ __forceinline__ void load_afrags(const char* sAbuf, int rb0, int g, int c,
                                            uint32_t* A0, uint32_t* A1,
                                            uint32_t* A2, uint32_t* A3)
{
    const char* a_lo = sAbuf + (rb0 + g) * 272 + c * 4;
    const char* a_hi = a_lo + 8 * 272;
    #pragma unroll
    for (int ks = 0; ks < 8; ks++) {
        A0[ks] = *(const uint32_t*)(a_lo + ks * 32);
        A2[ks] = *(const uint32_t*)(a_lo + ks * 32 + 16);
        A1[ks] = *(const uint32_t*)(a_hi + ks * 32);
        A3[ks] = *(const uint32_t*)(a_hi + ks * 32 + 16);
    }
}

// 8 col-tiles; B at [tt][q][lane]: addr = tt*2048 + q*512 + lane*16 (conflict-free)
__device__ __forceinline__ void mma_half(int tstart, const char* sB, int lane, int c,
    const uint32_t* A0, const uint32_t* A1, const uint32_t* A2, const uint32_t* A3,
    float sI0, float sI1, float invn0, float invn1, int lbl0, int lbl1,
    float& ac00, float& ac01, float& ac10, float& ac11, float& cs0, float& cs1)
{
    #pragma unroll
    for (int t = 0; t < 8; t++) {
        const int tt = tstart + t;
        float c0 = 0.f, c1 = 0.f, c2 = 0.f, c3 = 0.f;
        const char* bb = sB + tt * 2048 + lane * 16;
        #pragma unroll
        for (int q = 0; q < 4; q++) {
            const uint4 bv = *(const uint4*)(bb + q * 512);
            hmma16816(c0, c1, c2, c3,
                      A0[2*q], A1[2*q], A2[2*q], A3[2*q], bv.x, bv.y);
            hmma16816(c0, c1, c2, c3,
                      A0[2*q+1], A1[2*q+1], A2[2*q+1], A3[2*q+1], bv.z, bv.w);
        }
        const int n0 = 8 * tt + 2 * c;
        float e0 = ex2(fmaf(c0, sI0, -SH2));
        float e1 = ex2(fmaf(c1, sI0, -SH2));
        float e2 = ex2(fmaf(c2, sI1, -SH2));
        float e3 = ex2(fmaf(c3, sI1, -SH2));
        if (n0     == lbl0) { cs0 = c0 * invn0; e0 = 0.f; }
        if (n0 + 1 == lbl0) { cs0 = c1 * invn0; e1 = 0.f; }
        if (n0     == lbl1) { cs1 = c2 * invn1; e2 = 0.f; }
        if (n0 + 1 == lbl1) { cs1 = c3 * invn1; e3 = 0.f; }
        ac00 += e0; ac01 += e1; ac10 += e2; ac11 += e3;
    }
}

// ---------------------------------------------------------------------------
// main: 3 CTAs/SM persistent, predict-only register prefetch, compact B
// ---------------------------------------------------------------------------
__global__ void __launch_bounds__(256, 3)
arc_main(const float* __restrict__ predict,
         const float* __restrict__ target,
         float* __restrict__ out)
{
    extern __shared__ char sm[];
    char*  sA   = sm + OFF_A;
    char*  sB   = sm + OFF_B;
    float* red  = (float*)(sm + OFF_RED);
    int*   flag = (int*)(sm + OFF_FLAG);

    const int tid  = threadIdx.x;
    const int lane = tid & 31;
    const int w    = tid >> 5;
    const int g    = lane >> 2;
    const int c    = lane & 3;
    const int rb0  = w * 16;

    // ---- B tile: fragment-ordered compact copy ([t][q][lane], no pad) ----
    {
        const uint4* gw = (const uint4*)g_wfrag;    // 2048 uint4; src idx = (t*32+lane)*4+q
        #pragma unroll
        for (int i = 0; i < 8; i++) {
            int idx = i * 256 + tid;                // global uint4 index
            int q   = idx & 3, ln = (idx >> 2) & 31, t = idx >> 7;
            *(uint4*)(sB + t * 2048 + q * 512 + ln * 16) = gw[idx];
        }
    }
    __syncthreads();

    float4 Vp[8];
    uint32_t A0[8], A1[8], A2[8], A3[8];

    // ---- first tile prologue ----
    int tile = blockIdx.x;
    float ss0, ss1; int lbl0, lbl1;
    issue_p(predict, tile, rb0, lane, Vp);
    consume_half(Vp, target, tile, rb0, sA, lane, g, ss0, lbl0);
    issue_p(predict, tile, rb0 + 8, lane, Vp);
    consume_half(Vp, target, tile, rb0 + 8, sA, lane, g, ss1, lbl1);
    __syncwarp();
    load_afrags(sA, rb0, g, c, A0, A1, A2, A3);
    float invn0 = rsqrtf(fmaxf(ss0, 1e-24f));
    float invn1 = rsqrtf(fmaxf(ss1, 1e-24f));

    int  next    = tile + NPERS;
    bool hasNext = next < NTILES;
    if (hasNext) issue_p(predict, next, rb0, lane, Vp);

    float nll_acc = 0.f;
    float ns0 = 0.f, ns1 = 0.f; int nl0 = 0, nl1 = 0;

    while (true) {
        const float sI0 = Sv * invn0 * LOG2E, sI1 = Sv * invn1 * LOG2E;
        float ac00 = 0.f, ac01 = 0.f, ac10 = 0.f, ac11 = 0.f;
        float cs0 = -2.0f, cs1 = -2.0f;

        mma_half(0, sB, lane, c, A0, A1, A2, A3, sI0, sI1, invn0, invn1, lbl0, lbl1,
                 ac00, ac01, ac10, ac11, cs0, cs1);

        if (hasNext) {
            // A regs hold tile i; smem A rows are dead -> overwrite in place
            consume_half(Vp, target, next, rb0, sA, lane, g, ns0, nl0);
            issue_p(predict, next, rb0 + 8, lane, Vp);
        }

        mma_half(8, sB, lane, c, A0, A1, A2, A3, sI0, sI1, invn0, invn1, lbl0, lbl1,
                 ac00, ac01, ac10, ac11, cs0, cs1);

        // ---- tile epilogue ----
        float se0 = ac00 + ac01, se1 = ac10 + ac11;
        se0 += __shfl_xor_sync(0xffffffffu, se0, 1);
        se0 += __shfl_xor_sync(0xffffffffu, se0, 2);
        se1 += __shfl_xor_sync(0xffffffffu, se1, 1);
        se1 += __shfl_xor_sync(0xffffffffu, se1, 2);
        cs0 = fmaxf(cs0, __shfl_xor_sync(0xffffffffu, cs0, 1));
        cs0 = fmaxf(cs0, __shfl_xor_sync(0xffffffffu, cs0, 2));
        cs1 = fmaxf(cs1, __shfl_xor_sync(0xffffffffu, cs1, 1));
        cs1 = fmaxf(cs1, __shfl_xor_sync(0xffffffffu, cs1, 2));
        if (c == 0) nll_acc += row_nll(se0, cs0) + row_nll(se1, cs1);

        if (!hasNext) break;

        consume_half(Vp, target, next, rb0 + 8, sA, lane, g, ns1, nl1);
        __syncwarp();
        load_afrags(sA, rb0, g, c, A0, A1, A2, A3);
        invn0 = rsqrtf(fmaxf(ns0, 1e-24f));
        invn1 = rsqrtf(fmaxf(ns1, 1e-24f));
        lbl0 = nl0; lbl1 = nl1;

        tile = next; next += NPERS; hasNext = next < NTILES;
        if (hasNext) issue_p(predict, next, rb0, lane, Vp);
    }

    // ---- warp & block reduction of accumulated NLL ----
    float nll = nll_acc;
    #pragma unroll
    for (int o = 16; o; o >>= 1) nll += __shfl_xor_sync(0xffffffffu, nll, o);
    if (lane == 0) red[w] = nll;
    __syncthreads();

    if (tid == 0) {
        float t = 0.0f;
        #pragma unroll
        for (int i = 0; i < 8; i++) t += red[i];
        g_bsum[blockIdx.x] = t;
        __threadfence();
        int cdone = atomicAdd(&g_cnt, 1);
        *flag = (cdone == NPERS - 1) ? 1 : 0;
    }
    __syncthreads();

    // last CTA: deterministic final reduction -> mean
    if (*flag) {
        __threadfence();
        float t = 0.f;
        for (int i = tid; i < NPERS; i += 256) t += g_bsum[i];
        float* fr = (float*)sA;   // reuse smem
        fr[tid] = t;
        __syncthreads();
        #pragma unroll
        for (int st = 128; st; st >>= 1) {
            if (tid < st) fr[tid] += fr[tid + st];
            __syncthreads();
        }
        if (tid == 0) {
            out[0] = fr[0] / (float)Bn;
            g_cnt  = 0;
        }
    }
}

// ---------------------------------------------------------------------------
extern "C" void kernel_launch(void* const* d_in, const int* in_sizes, int n_in,
                              void* d_out, int out_size)
{
    (void)in_sizes; (void)n_in; (void)out_size;
    const float* predict = (const float*)d_in[0];
    const float* target  = (const float*)d_in[1];
    const float* weight  = (const float*)d_in[2];

    cudaFuncSetAttribute(arc_main, cudaFuncAttributeMaxDynamicSharedMemorySize, SMEM_SZ);

    prep_kernel<<<16, 256>>>(weight);
    arc_main<<<NPERS, 256, SMEM_SZ>>>(predict, target, (float*)d_out);
}

// round 11
// speedup vs baseline: 1.2455x; 1.2455x over previous
#include <cuda_runtime.h>
#include <cuda_fp16.h>
#include <cstdint>

// Problem constants
#define Bn 131072
#define Cn 128
#define En 128
#define TM 128              // samples per tile
#define NTILES (Bn / TM)    // 1024
#define NPERS 296           // persistent CTAs (2 per SM on 148 SMs)
#define THREADS 128         // 4 warps; each warp owns 32 rows

// ArcFace constants (m = 1.0, s = 100)
#define COSM 0.5403023058681398f
#define SINM 0.8414709848078965f
#define THv  (-0.5403023058681398f)
#define MMv  0.8414709848078965f
#define Sv   100.0f
#define SHIFT 30.0f
#define LOG2E 1.4426950408889634f
#define SH2   (SHIFT * LOG2E)

// Scratch (no allocation allowed -> device globals)
__device__ uint32_t g_wfrag[8192];   // 32KB: normalized weight fp16, HMMA fragment order
__device__ float    g_bsum[NPERS];
__device__ int      g_cnt;           // zero-init; reset by last CTA each launch

// smem layout
#define OFF_A    0                   // half[128][136], row stride 272B -> 34816 B
#define OFF_B    34816               // [tile][q][lane] uint4            -> 32768 B
#define OFF_RED  67584               // float[4]
#define OFF_FLAG 67600               // int
#define SMEM_SZ  67616

__device__ __forceinline__ float ex2(float x) {
    float r; asm("ex2.approx.f32 %0, %1;" : "=f"(r) : "f"(x)); return r;
}

__device__ __forceinline__ void hmma16816(float& c0, float& c1, float& c2, float& c3,
                                          uint32_t a0, uint32_t a1, uint32_t a2, uint32_t a3,
                                          uint32_t b0, uint32_t b1) {
    asm volatile(
        "mma.sync.aligned.m16n8k16.row.col.f32.f16.f16.f32 "
        "{%0,%1,%2,%3}, {%4,%5,%6,%7}, {%8,%9}, {%0,%1,%2,%3};"
        : "+f"(c0), "+f"(c1), "+f"(c2), "+f"(c3)
        : "r"(a0), "r"(a1), "r"(a2), "r"(a3), "r"(b0), "r"(b1));
}

// ---------------------------------------------------------------------------
// prep: normalize weight rows -> fragment-ordered fp16 global (as R9/R10)
// ---------------------------------------------------------------------------
__global__ void prep_kernel(const float* __restrict__ weight)
{
    const int lane = threadIdx.x & 31;
    const int w    = threadIdx.x >> 5;
    const int row  = blockIdx.x * 8 + w;          // class n
    const int g    = row & 7;
    const int t    = row >> 3;

    float4 v = reinterpret_cast<const float4*>(weight)[row * 32 + lane];
    float ss = v.x * v.x + v.y * v.y + v.z * v.z + v.w * v.w;
    #pragma unroll
    for (int o = 16; o; o >>= 1) ss += __shfl_xor_sync(0xffffffffu, ss, o);
    float r = 1.0f / fmaxf(sqrtf(ss), 1e-12f);

    __half2 h0 = __floats2half2_rn(v.x * r, v.y * r);   // halves m = 2*lane
    __half2 h1 = __floats2half2_rn(v.z * r, v.w * r);   // halves m = 2*lane+1

    #pragma unroll
    for (int j = 0; j < 2; j++) {
        const int m  = 2 * lane + j;                     // m = k/2 = 8ks+4b+c
        const int c  = m & 3, b = (m >> 2) & 1, ks = m >> 3;
        const int di = (t * 32 + g * 4 + c) * 16 + 2 * ks + b;
        g_wfrag[di] = (j == 0) ? *(uint32_t*)&h0 : *(uint32_t*)&h1;
    }
}

// NLL from label-EXCLUDED shifted sum se = sum exp(z-30), and label cosine cs.
__device__ __forceinline__ float row_nll(float se, float cs) {
    float sn  = sqrtf(fmaxf(1.0f - cs * cs, 0.0f));
    float phi = (cs > THv) ? (cs * COSM - sn * SINM) : (cs - MMv);
    float zl  = Sv * phi;
    float se2 = se + ex2(fmaf(zl, LOG2E, -SH2));
    return (SHIFT + __logf(se2)) - zl;
}

// prefetch 8 rows of predict+target (one chunk) into registers
__device__ __forceinline__ void issue_chunk(const float* __restrict__ predict,
                                            const float* __restrict__ target,
                                            int tile, int rowLocal, int lane,
                                            float4* Vp, float4* Vt)
{
    const size_t base = ((size_t)tile * TM + rowLocal) * 32 + lane;
    const float4* p4 = (const float4*)predict;
    const float4* t4 = (const float4*)target;
    #pragma unroll
    for (int j = 0; j < 8; j++) {
        Vp[j] = __ldg(p4 + base + (size_t)j * 32);
        Vt[j] = __ldg(t4 + base + (size_t)j * 32);
    }
}

// consume one 8-row chunk: fp16 convert + STS; ssq butterfly; ballot label
__device__ __forceinline__ void consume_chunk(const float4* Vp, const float4* Vt,
                                              char* sAbuf, int rowLocal, int lane, int g,
                                              float& ssOut, int& lblOut)
{
    float ssq[8];
    #pragma unroll
    for (int j = 0; j < 8; j++) {
        float4 v = Vp[j], t = Vt[j];
        __half2 h0 = __floats2half2_rn(v.x, v.y);
        __half2 h1 = __floats2half2_rn(v.z, v.w);
        unsigned long long pk;
        asm("mov.b64 %0,{%1,%2};" : "=l"(pk)
            : "r"(*(uint32_t*)&h0), "r"(*(uint32_t*)&h1));
        *reinterpret_cast<unsigned long long*>(sAbuf + (rowLocal + j) * 272 + lane * 8) = pk;
        ssq[j] = fmaf(v.x, v.x, fmaf(v.y, v.y, fmaf(v.z, v.z, v.w * v.w)));

        // ballot label: exactly one lane sees the one-hot 1.0 in its 4 values
        bool nz = (t.x > 0.5f) || (t.y > 0.5f) || (t.z > 0.5f) || (t.w > 0.5f);
        unsigned bal = __ballot_sync(0xffffffffu, nz);
        int li = (t.y > 0.5f) ? 1 : ((t.z > 0.5f) ? 2 : ((t.w > 0.5f) ? 3 : 0));
        int src = __ffs(bal) - 1;
        int lblj = 4 * src + __shfl_sync(0xffffffffu, li, src);
        if (j == g) lblOut = lblj;
    }
    #pragma unroll
    for (int o = 16; o; o >>= 1) {
        #pragma unroll
        for (int i = 0; i < 8; i++) ssq[i] += __shfl_xor_sync(0xffffffffu, ssq[i], o);
    }
    float ss = 0.f;
    #pragma unroll
    for (int i = 0; i < 8; i++) if (i == g) ss = ssq[i];
    ssOut = ss;
}

// load A fragments for one m16 block (rows base+g, base+g+8)
__device__ __forceinline__ void load_afrags(const char* sAbuf, int baseRow, int g, int c,
                                            uint32_t* A0, uint32_t* A1,
                                            uint32_t* A2, uint32_t* A3)
{
    const char* a_lo = sAbuf + (baseRow + g) * 272 + c * 4;
    const char* a_hi = a_lo + 8 * 272;
    #pragma unroll
    for (int ks = 0; ks < 8; ks++) {
        A0[ks] = *(const uint32_t*)(a_lo + ks * 32);
        A2[ks] = *(const uint32_t*)(a_lo + ks * 32 + 16);
        A1[ks] = *(const uint32_t*)(a_hi + ks * 32);
        A3[ks] = *(const uint32_t*)(a_hi + ks * 32 + 16);
    }
}

// 4 col-tiles: one B load feeds BOTH m16 blocks (2 independent HMMA chains)
__device__ __forceinline__ void mma_quarter(int tstart, const char* sB, int lane, int c,
    const uint32_t* A00, const uint32_t* A01, const uint32_t* A02, const uint32_t* A03,
    const uint32_t* A10, const uint32_t* A11, const uint32_t* A12, const uint32_t* A13,
    const float* sI, const float* invn, const int* lbl,
    float* ac, float* cs)
{
    #pragma unroll
    for (int t = 0; t < 4; t++) {
        const int tt = tstart + t;
        float x0 = 0.f, x1 = 0.f, x2 = 0.f, x3 = 0.f;
        float y0 = 0.f, y1 = 0.f, y2 = 0.f, y3 = 0.f;
        const char* bb = sB + tt * 2048 + lane * 16;
        #pragma unroll
        for (int q = 0; q < 4; q++) {
            const uint4 bv = *(const uint4*)(bb + q * 512);
            hmma16816(x0, x1, x2, x3, A00[2*q],   A01[2*q],   A02[2*q],   A03[2*q],   bv.x, bv.y);
            hmma16816(y0, y1, y2, y3, A10[2*q],   A11[2*q],   A12[2*q],   A13[2*q],   bv.x, bv.y);
            hmma16816(x0, x1, x2, x3, A00[2*q+1], A01[2*q+1], A02[2*q+1], A03[2*q+1], bv.z, bv.w);
            hmma16816(y0, y1, y2, y3, A10[2*q+1], A11[2*q+1], A12[2*q+1], A13[2*q+1], bv.z, bv.w);
        }
        const int n0 = 8 * tt + 2 * c;
        // chunk mapping: x0,x1->ch0 ; x2,x3->ch1 ; y0,y1->ch2 ; y2,y3->ch3
        float e0 = ex2(fmaf(x0, sI[0], -SH2));
        float e1 = ex2(fmaf(x1, sI[0], -SH2));
        float e2 = ex2(fmaf(x2, sI[1], -SH2));
        float e3 = ex2(fmaf(x3, sI[1], -SH2));
        float e4 = ex2(fmaf(y0, sI[2], -SH2));
        float e5 = ex2(fmaf(y1, sI[2], -SH2));
        float e6 = ex2(fmaf(y2, sI[3], -SH2));
        float e7 = ex2(fmaf(y3, sI[3], -SH2));
        if (n0     == lbl[0]) { cs[0] = x0 * invn[0]; e0 = 0.f; }
        if (n0 + 1 == lbl[0]) { cs[0] = x1 * invn[0]; e1 = 0.f; }
        if (n0     == lbl[1]) { cs[1] = x2 * invn[1]; e2 = 0.f; }
        if (n0 + 1 == lbl[1]) { cs[1] = x3 * invn[1]; e3 = 0.f; }
        if (n0     == lbl[2]) { cs[2] = y0 * invn[2]; e4 = 0.f; }
        if (n0 + 1 == lbl[2]) { cs[2] = y1 * invn[2]; e5 = 0.f; }
        if (n0     == lbl[3]) { cs[3] = y2 * invn[3]; e6 = 0.f; }
        if (n0 + 1 == lbl[3]) { cs[3] = y3 * invn[3]; e7 = 0.f; }
        ac[0] += e0; ac[1] += e1; ac[2] += e2; ac[3] += e3;
        ac[4] += e4; ac[5] += e5; ac[6] += e6; ac[7] += e7;
    }
}

// ---------------------------------------------------------------------------
// main: 128-thread persistent CTAs (2/SM), 32 rows/warp, chunked prefetch
// ---------------------------------------------------------------------------
__global__ void __launch_bounds__(THREADS, 2)
arc_main(const float* __restrict__ predict,
         const float* __restrict__ target,
         float* __restrict__ out)
{
    extern __shared__ char sm[];
    char*  sA   = sm + OFF_A;
    char*  sB   = sm + OFF_B;
    float* red  = (float*)(sm + OFF_RED);
    int*   flag = (int*)(sm + OFF_FLAG);

    const int tid  = threadIdx.x;
    const int lane = tid & 31;
    const int w    = tid >> 5;
    const int g    = lane >> 2;
    const int c    = lane & 3;
    const int rb   = w * 32;        // this warp's first row

    // ---- B tile: fragment-ordered compact copy ([t][q][lane]) ----
    {
        const uint4* gw = (const uint4*)g_wfrag;    // 2048 uint4
        #pragma unroll
        for (int i = 0; i < 16; i++) {
            int idx = i * 128 + tid;
            int q = idx & 3, ln = (idx >> 2) & 31, t = idx >> 7;
            *(uint4*)(sB + t * 2048 + q * 512 + ln * 16) = gw[idx];
        }
    }
    __syncthreads();

    float4 Vp[8], Vt[8];
    uint32_t A00[8], A01[8], A02[8], A03[8];   // block0: rows rb+g, rb+g+8
    uint32_t A10[8], A11[8], A12[8], A13[8];   // block1: rows rb+16+g, rb+24+g

    float invn[4], sI[4]; int lbl[4];
    float ns[4]; int nl[4];

    // ---- first tile prologue ----
    int tile = blockIdx.x;
    #pragma unroll
    for (int ch = 0; ch < 4; ch++) {
        issue_chunk(predict, target, tile, rb + 8 * ch, lane, Vp, Vt);
        float ss; int lb;
        consume_chunk(Vp, Vt, sA, rb + 8 * ch, lane, g, ss, lb);
        invn[ch] = rsqrtf(fmaxf(ss, 1e-24f));
        lbl[ch]  = lb;
    }
    __syncwarp();
    load_afrags(sA, rb,      g, c, A00, A01, A02, A03);
    load_afrags(sA, rb + 16, g, c, A10, A11, A12, A13);

    int  next    = tile + NPERS;
    bool hasNext = next < NTILES;
    if (hasNext) issue_chunk(predict, target, next, rb, lane, Vp, Vt);

    float nll_acc = 0.f;

    while (true) {
        #pragma unroll
        for (int ch = 0; ch < 4; ch++) sI[ch] = Sv * invn[ch] * LOG2E;
        float ac[8] = {0.f,0.f,0.f,0.f,0.f,0.f,0.f,0.f};
        float cs[4] = {-2.f,-2.f,-2.f,-2.f};

        mma_quarter(0, sB, lane, c, A00,A01,A02,A03, A10,A11,A12,A13,
                    sI, invn, lbl, ac, cs);
        if (hasNext) {
            consume_chunk(Vp, Vt, sA, rb, lane, g, ns[0], nl[0]);
            issue_chunk(predict, target, next, rb + 8, lane, Vp, Vt);
        }
        mma_quarter(4, sB, lane, c, A00,A01,A02,A03, A10,A11,A12,A13,
                    sI, invn, lbl, ac, cs);
        if (hasNext) {
            consume_chunk(Vp, Vt, sA, rb + 8, lane, g, ns[1], nl[1]);
            issue_chunk(predict, target, next, rb + 16, lane, Vp, Vt);
        }
        mma_quarter(8, sB, lane, c, A00,A01,A02,A03, A10,A11,A12,A13,
                    sI, invn, lbl, ac, cs);
        if (hasNext) {
            consume_chunk(Vp, Vt, sA, rb + 16, lane, g, ns[2], nl[2]);
            issue_chunk(predict, target, next, rb + 24, lane, Vp, Vt);
        }
        mma_quarter(12, sB, lane, c, A00,A01,A02,A03, A10,A11,A12,A13,
                    sI, invn, lbl, ac, cs);

        // ---- tile epilogue: 4 chunk-rows per lane ----
        #pragma unroll
        for (int ch = 0; ch < 4; ch++) {
            float se = ac[2*ch] + ac[2*ch+1];
            se += __shfl_xor_sync(0xffffffffu, se, 1);
            se += __shfl_xor_sync(0xffffffffu, se, 2);
            float cv = cs[ch];
            cv = fmaxf(cv, __shfl_xor_sync(0xffffffffu, cv, 1));
            cv = fmaxf(cv, __shfl_xor_sync(0xffffffffu, cv, 2));
            if (c == 0) nll_acc += row_nll(se, cv);
        }

        if (!hasNext) break;

        consume_chunk(Vp, Vt, sA, rb + 24, lane, g, ns[3], nl[3]);
        __syncwarp();
        load_afrags(sA, rb,      g, c, A00, A01, A02, A03);
        load_afrags(sA, rb + 16, g, c, A10, A11, A12, A13);
        #pragma unroll
        for (int ch = 0; ch < 4; ch++) {
            invn[ch] = rsqrtf(fmaxf(ns[ch], 1e-24f));
            lbl[ch]  = nl[ch];
        }

        tile = next; next += NPERS; hasNext = next < NTILES;
        if (hasNext) issue_chunk(predict, target, next, rb, lane, Vp, Vt);
    }

    // ---- warp & block reduction of accumulated NLL ----
    float nll = nll_acc;
    #pragma unroll
    for (int o = 16; o; o >>= 1) nll += __shfl_xor_sync(0xffffffffu, nll, o);
    if (lane == 0) red[w] = nll;
    __syncthreads();

    if (tid == 0) {
        float t = red[0] + red[1] + red[2] + red[3];
        g_bsum[blockIdx.x] = t;
        __threadfence();
        int cdone = atomicAdd(&g_cnt, 1);
        *flag = (cdone == NPERS - 1) ? 1 : 0;
    }
    __syncthreads();

    // last CTA: deterministic final reduction -> mean
    if (*flag) {
        __threadfence();
        float t = 0.f;
        for (int i = tid; i < NPERS; i += THREADS) t += g_bsum[i];
        float* fr = (float*)sA;   // reuse smem
        fr[tid] = t;
        __syncthreads();
        #pragma unroll
        for (int st = 64; st; st >>= 1) {
            if (tid < st) fr[tid] += fr[tid + st];
            __syncthreads();
        }
        if (tid == 0) {
            out[0] = fr[0] / (float)Bn;
            g_cnt  = 0;
        }
    }
}

// ---------------------------------------------------------------------------
extern "C" void kernel_launch(void* const* d_in, const int* in_sizes, int n_in,
                              void* d_out, int out_size)
{
    (void)in_sizes; (void)n_in; (void)out_size;
    const float* predict = (const float*)d_in[0];
    const float* target  = (const float*)d_in[1];
    const float* weight  = (const float*)d_in[2];

    cudaFuncSetAttribute(arc_main, cudaFuncAttributeMaxDynamicSharedMemorySize, SMEM_SZ);

    prep_kernel<<<16, 256>>>(weight);
    arc_main<<<NPERS, THREADS, SMEM_SZ>>>(predict, target, (float*)d_out);
}

// round 12
// speedup vs baseline: 1.3682x; 1.0985x over previous
#include <cuda_runtime.h>
#include <cuda_fp16.h>
#include <cstdint>

// Problem constants
#define Bn 131072
#define Cn 128
#define En 128
#define TM 128              // samples per tile
#define NTILES (Bn / TM)    // 1024
#define NPERS 296           // persistent CTAs (2 per SM on 148 SMs)

// ArcFace constants (m = 1.0, s = 100)
#define COSM 0.5403023058681398f
#define SINM 0.8414709848078965f
#define THv  (-0.5403023058681398f)
#define MMv  0.8414709848078965f
#define Sv   100.0f
#define SHIFT 30.0f                 // exp(z-30): no overflow, no harmful underflow
#define LOG2E 1.4426950408889634f
#define SH2   (SHIFT * LOG2E)

// Scratch (no allocation allowed -> device globals)
__device__ uint32_t g_wfrag[8192];   // 32KB: normalized weight fp16, HMMA fragment order
__device__ float    g_bsum[NPERS];
__device__ int      g_cnt;           // zero-init; reset by last CTA each launch
__device__ int      g_ready;         // weight-prep release counter (16 CTAs)

// smem layout
//   A: half[128][136] rows stride 272B              -> 34816 B
//   B: fragment order, 512 lane-rows x 80B stride   -> 40960 B
#define OFF_A    0
#define OFF_B    34816
#define OFF_RED  75776               // float[8]
#define OFF_FLAG 75808               // int
#define SMEM_SZ  75840

__device__ __forceinline__ float ex2(float x) {
    float r; asm("ex2.approx.f32 %0, %1;" : "=f"(r) : "f"(x)); return r;
}

__device__ __forceinline__ void hmma16816(float& c0, float& c1, float& c2, float& c3,
                                          uint32_t a0, uint32_t a1, uint32_t a2, uint32_t a3,
                                          uint32_t b0, uint32_t b1) {
    asm volatile(
        "mma.sync.aligned.m16n8k16.row.col.f32.f16.f16.f32 "
        "{%0,%1,%2,%3}, {%4,%5,%6,%7}, {%8,%9}, {%0,%1,%2,%3};"
        : "+f"(c0), "+f"(c1), "+f"(c2), "+f"(c3)
        : "r"(a0), "r"(a1), "r"(a2), "r"(a3), "r"(b0), "r"(b1));
}

// NLL from label-EXCLUDED shifted sum se = sum exp(z-30), and label cosine cs.
__device__ __forceinline__ float row_nll(float se, float cs) {
    float sn  = sqrtf(fmaxf(1.0f - cs * cs, 0.0f));
    float phi = (cs > THv) ? (cs * COSM - sn * SINM) : (cs - MMv);
    float zl  = Sv * phi;
    float se2 = se + ex2(fmaf(zl, LOG2E, -SH2));
    return (SHIFT + __logf(se2)) - zl;
}

// prefetch 8 rows of predict+target into registers
__device__ __forceinline__ void issue_half(const float* __restrict__ predict,
                                           const float* __restrict__ target,
                                           int tile, int rowLocal, int lane,
                                           float4* Vp, float4* Vt)
{
    const size_t base = ((size_t)tile * TM + rowLocal) * 32 + lane;
    const float4* p4 = (const float4*)predict;
    const float4* t4 = (const float4*)target;
    #pragma unroll
    for (int j = 0; j < 8; j++) {
        Vp[j] = __ldg(p4 + base + (size_t)j * 32);
        Vt[j] = __ldg(t4 + base + (size_t)j * 32);
    }
}

// consume 8 prefetched rows: fp16 convert + STS; ssq butterfly; ballot label
__device__ __forceinline__ void consume_half(const float4* Vp, const float4* Vt,
                                             char* sAbuf, int rowLocal, int lane, int g,
                                             float& ssOut, int& lblOut)
{
    float ssq[8];
    #pragma unroll
    for (int j = 0; j < 8; j++) {
        float4 v = Vp[j], t = Vt[j];
        __half2 h0 = __floats2half2_rn(v.x, v.y);
        __half2 h1 = __floats2half2_rn(v.z, v.w);
        unsigned long long pk;
        asm("mov.b64 %0,{%1,%2};" : "=l"(pk)
            : "r"(*(uint32_t*)&h0), "r"(*(uint32_t*)&h1));
        *reinterpret_cast<unsigned long long*>(sAbuf + (rowLocal + j) * 272 + lane * 8) = pk;
        ssq[j] = fmaf(v.x, v.x, fmaf(v.y, v.y, fmaf(v.z, v.z, v.w * v.w)));

        // ballot label: exactly one lane sees the one-hot 1.0 among its 4 values
        bool nz = (t.x > 0.5f) || (t.y > 0.5f) || (t.z > 0.5f) || (t.w > 0.5f);
        unsigned bal = __ballot_sync(0xffffffffu, nz);
        int li = (t.y > 0.5f) ? 1 : ((t.z > 0.5f) ? 2 : ((t.w > 0.5f) ? 3 : 0));
        int src = __ffs(bal) - 1;
        int lblj = 4 * src + __shfl_sync(0xffffffffu, li, src);
        if (j == g) lblOut = lblj;
    }
    #pragma unroll
    for (int o = 16; o; o >>= 1) {
        #pragma unroll
        for (int i = 0; i < 8; i++) ssq[i] += __shfl_xor_sync(0xffffffffu, ssq[i], o);
    }
    float ss = 0.f;
    #pragma unroll
    for (int i = 0; i < 8; i++) if (i == g) ss = ssq[i];
    ssOut = ss;
}

__device__ __forceinline__ void load_afrags(const char* sAbuf, int rb0, int g, int c,
                                            uint32_t* A0, uint32_t* A1,
                                            uint32_t* A2, uint32_t* A3)
{
    const char* a_lo = sAbuf + (rb0 + g) * 272 + c * 4;
    const char* a_hi = a_lo + 8 * 272;
    #pragma unroll
    for (int ks = 0; ks < 8; ks++) {
        A0[ks] = *(const uint32_t*)(a_lo + ks * 32);
        A2[ks] = *(const uint32_t*)(a_lo + ks * 32 + 16);
        A1[ks] = *(const uint32_t*)(a_hi + ks * 32);
        A3[ks] = *(const uint32_t*)(a_hi + ks * 32 + 16);
    }
}

// 8 col-tiles; B via LDS.128 fragment loads (80B lane stride, conflict-free)
__device__ __forceinline__ void mma_half(int tstart, const char* sB, int lane, int c,
    const uint32_t* A0, const uint32_t* A1, const uint32_t* A2, const uint32_t* A3,
    float sI0, float sI1, float invn0, float invn1, int lbl0, int lbl1,
    float& ac00, float& ac01, float& ac10, float& ac11, float& cs0, float& cs1)
{
    #pragma unroll
    for (int t = 0; t < 8; t++) {
        const int tt = tstart + t;
        float c0 = 0.f, c1 = 0.f, c2 = 0.f, c3 = 0.f;
        const char* bb = sB + (tt * 32 + lane) * 80;
        #pragma unroll
        for (int q = 0; q < 4; q++) {
            const uint4 bv = *(const uint4*)(bb + q * 16);
            hmma16816(c0, c1, c2, c3,
                      A0[2*q], A1[2*q], A2[2*q], A3[2*q], bv.x, bv.y);
            hmma16816(c0, c1, c2, c3,
                      A0[2*q+1], A1[2*q+1], A2[2*q+1], A3[2*q+1], bv.z, bv.w);
        }
        const int n0 = 8 * tt + 2 * c;
        float e0 = ex2(fmaf(c0, sI0, -SH2));
        float e1 = ex2(fmaf(c1, sI0, -SH2));
        float e2 = ex2(fmaf(c2, sI1, -SH2));
        float e3 = ex2(fmaf(c3, sI1, -SH2));
        if (n0     == lbl0) { cs0 = c0 * invn0; e0 = 0.f; }
        if (n0 + 1 == lbl0) { cs0 = c1 * invn0; e1 = 0.f; }
        if (n0     == lbl1) { cs1 = c2 * invn1; e2 = 0.f; }
        if (n0 + 1 == lbl1) { cs1 = c3 * invn1; e3 = 0.f; }
        ac00 += e0; ac01 += e1; ac10 += e2; ac11 += e3;
    }
}

// ---------------------------------------------------------------------------
// single fused kernel: CTAs 0-15 prep weights, all CTAs persistent-loop tiles
// ---------------------------------------------------------------------------
__global__ void __launch_bounds__(256, 2)
arc_main(const float* __restrict__ predict,
         const float* __restrict__ target,
         const float* __restrict__ weight,
         float* __restrict__ out)
{
    extern __shared__ char sm[];
    char*  sA   = sm + OFF_A;
    char*  sB   = sm + OFF_B;
    float* red  = (float*)(sm + OFF_RED);
    int*   flag = (int*)(sm + OFF_FLAG);

    const int tid  = threadIdx.x;
    const int lane = tid & 31;
    const int w    = tid >> 5;
    const int g    = lane >> 2;
    const int c    = lane & 3;
    const int rb0  = w * 16;
    const int blk  = blockIdx.x;

    // ---- distributed weight prep: CTAs 0..15, one warp per weight row ----
    if (blk < 16) {
        const int row = blk * 8 + w;               // class n
        const int gg  = row & 7;
        const int tt  = row >> 3;
        float4 v = reinterpret_cast<const float4*>(weight)[row * 32 + lane];
        float ss = v.x * v.x + v.y * v.y + v.z * v.z + v.w * v.w;
        #pragma unroll
        for (int o = 16; o; o >>= 1) ss += __shfl_xor_sync(0xffffffffu, ss, o);
        float r = 1.0f / fmaxf(sqrtf(ss), 1e-12f);
        __half2 h0 = __floats2half2_rn(v.x * r, v.y * r);   // halves m = 2*lane
        __half2 h1 = __floats2half2_rn(v.z * r, v.w * r);   // halves m = 2*lane+1
        #pragma unroll
        for (int j = 0; j < 2; j++) {
            const int m  = 2 * lane + j;                     // m = k/2 = 8ks+4b+cc
            const int cc = m & 3, b = (m >> 2) & 1, ks = m >> 3;
            const int di = (tt * 32 + gg * 4 + cc) * 16 + 2 * ks + b;
            g_wfrag[di] = (j == 0) ? *(uint32_t*)&h0 : *(uint32_t*)&h1;
        }
        __threadfence();
        __syncthreads();
        if (tid == 0) atomicAdd(&g_ready, 1);
    }

    float4 Vp[8], Vt[8];
    uint32_t A0[8], A1[8], A2[8], A3[8];

    // ---- first tile prologue (no B dependence) ----
    int tile = blk;
    float ss0, ss1; int lbl0 = 0, lbl1 = 0;
    issue_half(predict, target, tile, rb0, lane, Vp, Vt);
    consume_half(Vp, Vt, sA, rb0, lane, g, ss0, lbl0);
    issue_half(predict, target, tile, rb0 + 8, lane, Vp, Vt);
    consume_half(Vp, Vt, sA, rb0 + 8, lane, g, ss1, lbl1);
    __syncwarp();
    load_afrags(sA, rb0, g, c, A0, A1, A2, A3);
    float invn0 = rsqrtf(fmaxf(ss0, 1e-24f));
    float invn1 = rsqrtf(fmaxf(ss1, 1e-24f));

    int  next    = tile + NPERS;
    bool hasNext = next < NTILES;
    if (hasNext) issue_half(predict, target, next, rb0, lane, Vp, Vt);

    // ---- wait for weight prep, then stage B (spin is hidden by prologue) ----
    if (tid == 0) { while (atomicAdd(&g_ready, 0) < 16) { } }
    __syncthreads();
    {
        const uint4* gw = (const uint4*)g_wfrag;    // 2048 uint4
        #pragma unroll
        for (int i = 0; i < 8; i++) {
            int idx = i * 256 + tid;
            *(uint4*)(sB + (idx >> 2) * 80 + (idx & 3) * 16) = gw[idx];
        }
    }
    __syncthreads();

    float nll_acc = 0.f;
    float ns0 = 0.f, ns1 = 0.f; int nl0 = 0, nl1 = 0;

    while (true) {
        const float sI0 = Sv * invn0 * LOG2E, sI1 = Sv * invn1 * LOG2E;
        float ac00 = 0.f, ac01 = 0.f, ac10 = 0.f, ac11 = 0.f;
        float cs0 = -2.0f, cs1 = -2.0f;

        mma_half(0, sB, lane, c, A0, A1, A2, A3, sI0, sI1, invn0, invn1, lbl0, lbl1,
                 ac00, ac01, ac10, ac11, cs0, cs1);

        if (hasNext) {
            // A regs hold tile i; smem A rows are dead -> overwrite in place
            consume_half(Vp, Vt, sA, rb0, lane, g, ns0, nl0);
            issue_half(predict, target, next, rb0 + 8, lane, Vp, Vt);
        }

        mma_half(8, sB, lane, c, A0, A1, A2, A3, sI0, sI1, invn0, invn1, lbl0, lbl1,
                 ac00, ac01, ac10, ac11, cs0, cs1);

        // ---- tile epilogue ----
        float se0 = ac00 + ac01, se1 = ac10 + ac11;
        se0 += __shfl_xor_sync(0xffffffffu, se0, 1);
        se0 += __shfl_xor_sync(0xffffffffu, se0, 2);
        se1 += __shfl_xor_sync(0xffffffffu, se1, 1);
        se1 += __shfl_xor_sync(0xffffffffu, se1, 2);
        cs0 = fmaxf(cs0, __shfl_xor_sync(0xffffffffu, cs0, 1));
        cs0 = fmaxf(cs0, __shfl_xor_sync(0xffffffffu, cs0, 2));
        cs1 = fmaxf(cs1, __shfl_xor_sync(0xffffffffu, cs1, 1));
        cs1 = fmaxf(cs1, __shfl_xor_sync(0xffffffffu, cs1, 2));
        if (c == 0) nll_acc += row_nll(se0, cs0) + row_nll(se1, cs1);

        if (!hasNext) break;

        consume_half(Vp, Vt, sA, rb0 + 8, lane, g, ns1, nl1);
        __syncwarp();
        load_afrags(sA, rb0, g, c, A0, A1, A2, A3);
        invn0 = rsqrtf(fmaxf(ns0, 1e-24f));
        invn1 = rsqrtf(fmaxf(ns1, 1e-24f));
        lbl0 = nl0; lbl1 = nl1;

        tile = next; next += NPERS; hasNext = next < NTILES;
        if (hasNext) issue_half(predict, target, next, rb0, lane, Vp, Vt);
    }

    // ---- warp & block reduction of accumulated NLL ----
    float nll = nll_acc;
    #pragma unroll
    for (int o = 16; o; o >>= 1) nll += __shfl_xor_sync(0xffffffffu, nll, o);
    if (lane == 0) red[w] = nll;
    __syncthreads();

    if (tid == 0) {
        float t = 0.0f;
        #pragma unroll
        for (int i = 0; i < 8; i++) t += red[i];
        g_bsum[blk] = t;
        __threadfence();
        int cdone = atomicAdd(&g_cnt, 1);
        *flag = (cdone == NPERS - 1) ? 1 : 0;
    }
    __syncthreads();

    // last CTA: deterministic final reduction -> mean; reset counters
    if (*flag) {
        __threadfence();
        float t = g_bsum[tid];
        if (tid + 256 < NPERS) t += g_bsum[tid + 256];
        float* fr = (float*)sA;   // reuse smem
        fr[tid] = t;
        __syncthreads();
        #pragma unroll
        for (int st = 128; st; st >>= 1) {
            if (tid < st) fr[tid] += fr[tid + st];
            __syncthreads();
        }
        if (tid == 0) {
            out[0]  = fr[0] / (float)Bn;
            g_cnt   = 0;
            g_ready = 0;
        }
    }
}

// ---------------------------------------------------------------------------
extern "C" void kernel_launch(void* const* d_in, const int* in_sizes, int n_in,
                              void* d_out, int out_size)
{
    (void)in_sizes; (void)n_in; (void)out_size;
    const float* predict = (const float*)d_in[0];
    const float* target  = (const float*)d_in[1];
    const float* weight  = (const float*)d_in[2];

    cudaFuncSetAttribute(arc_main, cudaFuncAttributeMaxDynamicSharedMemorySize, SMEM_SZ);

    arc_main<<<NPERS, 256, SMEM_SZ>>>(predict, target, weight, (float*)d_out);
}